// round 5
// baseline (speedup 1.0000x reference)
#include <cuda_runtime.h>

// Direct 3x3 valid conv, stride 1.
//   x:   (64, 224, 224)  f32
//   w:   (128, 64, 3, 3) f32
//   out: (128, 222, 222) f32
//
// Register-tiled: each thread computes 4 output pixels (width) x 8 output
// channels. Block tile: 64W x 8H x 16 out-channels, 256 threads.
// Input channels staged through shared memory in chunks of 8; weights staged
// transposed [ci][tap][co] so per-warp weight reads are broadcasts.

#define C_IN   64
#define H_IN   224
#define W_IN   224
#define C_OUT  128
#define H_OUT  222
#define W_OUT  222

#define BW 64      // output cols per block
#define BH 8       // output rows per block
#define BC 16      // output channels per block
#define CK 8       // input channels per smem chunk

#define IN_TW (BW + 2)          // 66 patch cols
#define IN_TH (BH + 2)          // 10 patch rows
#define IN_STRIDE 68            // padded row stride (floats)

__global__ __launch_bounds__(256)
void conv3x3_kernel(const float* __restrict__ x,
                    const float* __restrict__ w,
                    float* __restrict__ out)
{
    __shared__ float s_in[CK][IN_TH][IN_STRIDE];   // 21,760 B
    __shared__ float s_w[CK][9][BC];               //  4,608 B

    const int tid    = threadIdx.x;
    const int tileX  = blockIdx.x;   // 0..3   (64-wide tiles over 222)
    const int tileY  = blockIdx.y;   // 0..27  (8-high tiles over 222)
    const int coTile = blockIdx.z;   // 0..7   (16-channel groups over 128)

    const int tx = tid & 15;         // 16 -> 4 px each = 64 cols
    const int ty = (tid >> 4) & 7;   // 8 rows
    const int tz = tid >> 7;         // 2 -> 8 co each = 16 channels
                                     // NOTE: tz constant within a warp -> weight broadcast

    const int ox0    = tileX * BW + tx * 4;
    const int oy     = tileY * BH + ty;
    const int coBase = coTile * BC;

    float acc[8][4];
#pragma unroll
    for (int f = 0; f < 8; f++)
#pragma unroll
        for (int p = 0; p < 4; p++) acc[f][p] = 0.0f;

    for (int cc = 0; cc < C_IN; cc += CK) {
        __syncthreads();   // previous chunk's compute done before smem overwrite

        // ---- stage input patch: CK channels x 10 rows x 66 cols ----
        for (int i = tid; i < CK * IN_TH * IN_TW; i += 256) {
            int ci  = i / (IN_TH * IN_TW);
            int rem = i - ci * (IN_TH * IN_TW);
            int row = rem / IN_TW;
            int col = rem - row * IN_TW;
            int gy  = tileY * BH + row;
            int gx  = tileX * BW + col;
            float v = 0.0f;
            if (gy < H_IN && gx < W_IN)
                v = x[((cc + ci) * H_IN + gy) * W_IN + gx];
            s_in[ci][row][col] = v;
        }

        // ---- stage weights transposed: [ci][tap][co] ----
        for (int i = tid; i < CK * 9 * BC; i += 256) {
            int ci  = i / (9 * BC);
            int rem = i - ci * 9 * BC;
            int rs  = rem / BC;
            int co  = rem - rs * BC;
            s_w[ci][rs][co] = w[((coBase + co) * C_IN + (cc + ci)) * 9 + rs];
        }
        __syncthreads();

        // ---- compute: keep body small (no ci unroll) so it fits L0 I$ ----
#pragma unroll 1
        for (int ci = 0; ci < CK; ci++) {
#pragma unroll
            for (int r = 0; r < 3; r++) {
                float xv[6];
                const float* rowp = &s_in[ci][ty + r][tx * 4];
#pragma unroll
                for (int q = 0; q < 6; q++) xv[q] = rowp[q];
#pragma unroll
                for (int s = 0; s < 3; s++) {
                    const float* wp = &s_w[ci][r * 3 + s][tz * 8];
#pragma unroll
                    for (int f = 0; f < 8; f++) {
                        float wf = wp[f];   // warp-uniform broadcast LDS
#pragma unroll
                        for (int p = 0; p < 4; p++)
                            acc[f][p] = fmaf(wf, xv[s + p], acc[f][p]);
                    }
                }
            }
        }
    }

    // ---- epilogue ----
    if (oy < H_OUT) {
#pragma unroll
        for (int f = 0; f < 8; f++) {
            int co = coBase + tz * 8 + f;
            float* orow = &out[(co * H_OUT + oy) * W_OUT];
#pragma unroll
            for (int p = 0; p < 4; p++) {
                int ox = ox0 + p;
                if (ox < W_OUT) orow[ox] = acc[f][p];
            }
        }
    }
}

extern "C" void kernel_launch(void* const* d_in, const int* in_sizes, int n_in,
                              void* d_out, int out_size)
{
    const float* x = (const float*)d_in[0];
    const float* w = (const float*)d_in[1];
    // Defensive: if metadata order is (kernels, x), swap by element count.
    if (n_in >= 2 && in_sizes[0] == C_OUT * C_IN * 9 &&
        in_sizes[1] == C_IN * H_IN * W_IN) {
        w = (const float*)d_in[0];
        x = (const float*)d_in[1];
    }
    float* out = (float*)d_out;

    dim3 grid((W_OUT + BW - 1) / BW,    // 4
              (H_OUT + BH - 1) / BH,    // 28
              C_OUT / BC);              // 8
    conv3x3_kernel<<<grid, 256>>>(x, w, out);
}

// round 9
// speedup vs baseline: 2.2025x; 2.2025x over previous
#include <cuda_runtime.h>
#include <cstdint>

// tf32 mma.sync (legacy HMMA path; tcgen05 is 'a'-gated and the build targets
// plain sm_103) implicit-GEMM 3x3 valid conv.
//   x: (64,224,224) f32, w: (128,64,3,3) f32 -> out: (128,222,222) f32
// GEMM: D[co][n] = sum_k A[co][k]*B[n][k],  k = tap*64+ci, n = output pixel.

#define HW_IN  224
#define HW_OUT 222
#define C_IN   64
#define C_OUT  128
#define NCH    18            // K=576 in chunks of 32

#define SWZ(o) ((o) ^ (((o) >> 3) & 0x70))

// smem: buf0 {A@0,B@16K}, buf1 {A@32K,B@48K}
#define SA(b) ((b) * 32768u)
#define SB(b) ((b) * 32768u + 16384u)
#define SM_TOTAL 65536

__device__ __forceinline__ uint32_t smem_u32(const void* p) {
    uint32_t a;
    asm("{ .reg .u64 t; cvta.to.shared.u64 t, %1; cvt.u32.u64 %0, t; }" : "=r"(a) : "l"(p));
    return a;
}
__device__ __forceinline__ uint32_t f2tf32(float v) {
    uint32_t r; asm("cvt.rna.tf32.f32 %0, %1;" : "=r"(r) : "f"(v)); return r;
}
__device__ __forceinline__ void sts32(uint32_t a, uint32_t v) {
    asm volatile("st.shared.b32 [%0], %1;" :: "r"(a), "r"(v) : "memory");
}
__device__ __forceinline__ void ldsm4(uint32_t* d, uint32_t a) {
    asm volatile("ldmatrix.sync.aligned.m8n8.x4.shared.b16 {%0,%1,%2,%3}, [%4];"
                 : "=r"(d[0]), "=r"(d[1]), "=r"(d[2]), "=r"(d[3]) : "r"(a));
}
__device__ __forceinline__ void mma8(float* c, const uint32_t* a, uint32_t b0, uint32_t b1) {
    asm volatile("mma.sync.aligned.m16n8k8.row.col.f32.tf32.tf32.f32 "
                 "{%0,%1,%2,%3}, {%4,%5,%6,%7}, {%8,%9}, {%0,%1,%2,%3};"
                 : "+f"(c[0]), "+f"(c[1]), "+f"(c[2]), "+f"(c[3])
                 : "r"(a[0]), "r"(a[1]), "r"(a[2]), "r"(a[3]), "r"(b0), "r"(b1));
}

__global__ __launch_bounds__(256, 2)
void conv_mma_kernel(const float* __restrict__ x,
                     const float* __restrict__ w,
                     float* __restrict__ out)
{
    extern __shared__ char smem[];
    const uint32_t sb = smem_u32(smem);
    const int tid  = threadIdx.x, wid = tid >> 5, lane = tid & 31;
    const int oy   = blockIdx.y;
    const int bx   = blockIdx.x;          // 0: cols 0..111, 1: cols 112..221
    const int n0   = bx * 112;

    const int warp_m = (wid & 1) * 64;    // co block
    const int warp_n = (wid >> 1) * 32;   // pixel block
    const int mi = lane >> 3, ri = lane & 7;

    // pre-swizzle byte offsets for ldmatrix row addressing (k varies per step)
    uint32_t a_off[4], b_off[2];
#pragma unroll
    for (int i = 0; i < 4; i++)
        a_off[i] = (uint32_t)(warp_m + i * 16 + (mi & 1) * 8 + ri) * 128u + (uint32_t)(mi >> 1) * 16u;
#pragma unroll
    for (int p = 0; p < 2; p++)
        b_off[p] = (uint32_t)(warp_n + p * 16 + (mi >> 1) * 8 + ri) * 128u + (uint32_t)(mi & 1) * 16u;

    float acc[4][4][4];
#pragma unroll
    for (int i = 0; i < 4; i++)
#pragma unroll
        for (int j = 0; j < 4; j++)
#pragma unroll
            for (int q = 0; q < 4; q++) acc[i][j][q] = 0.0f;

#pragma unroll 1
    for (int c = 0; c < NCH; c++) {
        const int buf = c & 1;
        const int tap = c >> 1;
        const int ci0 = (c & 1) * 32;
        const int r   = tap / 3, s = tap - 3 * r;
        const int gy  = oy + r;                 // <= 223, always valid
        const uint32_t abase = sb + SA(buf);
        const uint32_t bbase = sb + SB(buf);

        // ---- stage A: [co][kk] = w[co][ci0+kk][tap], kk-contiguous, SW128 ----
#pragma unroll
        for (int t = 0; t < 16; t++) {
            int i  = tid + t * 256;
            int co = i >> 5, kk = i & 31;       // per warp: one co, kk = lane (conflict-free STS)
            float v = w[co * 576 + (ci0 + kk) * 9 + tap];
            sts32(abase + SWZ((uint32_t)(co * 128 + kk * 4)), f2tf32(v));
        }
        // ---- stage B: [n][kk] = x[ci0+kk][gy][n0+n+s] (zero past width) ----
        const float* xp = x + (size_t)ci0 * (HW_IN * HW_IN) + (size_t)gy * HW_IN + n0 + s;
#pragma unroll
        for (int t = 0; t < 16; t++) {
            int i  = tid + t * 256;
            int kk = i >> 7, n = i & 127;       // coalesced LDG along n
            float v = (n0 + n + s < HW_IN) ? xp[kk * (HW_IN * HW_IN) + n] : 0.0f;
            sts32(bbase + SWZ((uint32_t)(n * 128 + kk * 4)), f2tf32(v));
        }
        __syncthreads();   // single barrier per chunk (double-buffer safe)

        // ---- compute: 4 k-steps of K=8 ----
#pragma unroll
        for (int ks = 0; ks < 4; ks++) {
            const uint32_t kb = (uint32_t)ks * 32u;
            uint32_t afr[4][4], bfr[2][4];
#pragma unroll
            for (int i = 0; i < 4; i++) ldsm4(afr[i], abase + SWZ(a_off[i] + kb));
#pragma unroll
            for (int p = 0; p < 2; p++) ldsm4(bfr[p], bbase + SWZ(b_off[p] + kb));
#pragma unroll
            for (int i = 0; i < 4; i++)
#pragma unroll
                for (int j = 0; j < 4; j++)
                    mma8(acc[i][j], afr[i], bfr[j >> 1][(j & 1) * 2], bfr[j >> 1][(j & 1) * 2 + 1]);
        }
    }

    // ---- epilogue: direct STG from fragments ----
    const int jmax = bx ? 110 : 112;          // cols this block owns
    const int gid = lane >> 2, tig = lane & 3;
#pragma unroll
    for (int i = 0; i < 4; i++) {
#pragma unroll
        for (int j = 0; j < 4; j++) {
            int cb = warp_n + j * 8 + tig * 2;   // even
            if (cb < jmax) {
                int ox  = n0 + cb;
                size_t rowoff = (size_t)oy * HW_OUT + ox;
                int co0 = warp_m + i * 16 + gid;
                int co1 = co0 + 8;
                float2 v0 = make_float2(acc[i][j][0], acc[i][j][1]);
                float2 v1 = make_float2(acc[i][j][2], acc[i][j][3]);
                *(float2*)&out[(size_t)co0 * (HW_OUT * HW_OUT) + rowoff] = v0;
                *(float2*)&out[(size_t)co1 * (HW_OUT * HW_OUT) + rowoff] = v1;
            }
        }
    }
}

extern "C" void kernel_launch(void* const* d_in, const int* in_sizes, int n_in,
                              void* d_out, int out_size)
{
    const float* x = (const float*)d_in[0];
    const float* w = (const float*)d_in[1];
    if (n_in >= 2 && in_sizes[0] == C_OUT * C_IN * 9 &&
        in_sizes[1] == C_IN * HW_IN * HW_IN) {
        w = (const float*)d_in[0];
        x = (const float*)d_in[1];
    }
    float* out = (float*)d_out;

    static int attr_set = 0;
    (void)attr_set;  // cudaFuncSetAttribute is idempotent & capture-safe; call every time
    cudaFuncSetAttribute(conv_mma_kernel,
                         cudaFuncAttributeMaxDynamicSharedMemorySize, SM_TOTAL);

    dim3 grid(2, HW_OUT);
    conv_mma_kernel<<<grid, 256, SM_TOTAL>>>(x, w, out);
}

// round 10
// speedup vs baseline: 4.0207x; 1.8255x over previous
#include <cuda_runtime.h>
#include <cstdint>

// tf32 mma.sync implicit-GEMM 3x3 valid conv with cp.async 3-stage pipeline.
//   x: (64,224,224) f32, w: (128,64,3,3) f32 -> out: (128,222,222) f32
// Pre-pass converts to tf32 GEMM-friendly layouts:
//   xt[y][col][ci]  (col padded to 228, pad cols stay zero)
//   wt[tap][co][ci]
// Main GEMM: D[co][n] = sum_k A[co][k]*B[n][k], k=(tap,ci), chunks of 32.
// Tiles: M=64 (co half, grid.z) x N=112 (grid.x) per row oy (grid.y).
// grid = 2*222*2 = 888 = 148 SMs * 3 CTAs * 2 waves (exact).

#define HW_IN  224
#define HW_OUT 222
#define C_IN   64
#define C_OUT  128
#define XT_W   228
#define NCH    18
#define OUT_HW (HW_OUT * HW_OUT)

#define SWZ(o) ((o) ^ (((o) >> 3) & 0x70))

#define STG_BYTES 22528u        // A 8KB + B 14KB per stage
#define SM_MAIN   (3 * STG_BYTES)

__device__ float wt_g[9 * 128 * 64];          // 294,912 B
__device__ float xt_g[224 * XT_W * 64];       // 13.07 MB, zero-initialized

__device__ __forceinline__ uint32_t smem_u32(const void* p) {
    uint32_t a;
    asm("{ .reg .u64 t; cvta.to.shared.u64 t, %1; cvt.u32.u64 %0, t; }" : "=r"(a) : "l"(p));
    return a;
}
__device__ __forceinline__ float f2tf32(float v) {
    uint32_t r; asm("cvt.rna.tf32.f32 %0, %1;" : "=r"(r) : "f"(v));
    return __uint_as_float(r);
}
__device__ __forceinline__ void cp16(uint32_t dst, const float* src) {
    asm volatile("cp.async.cg.shared.global [%0], [%1], 16;" :: "r"(dst), "l"(src) : "memory");
}
#define CP_COMMIT() asm volatile("cp.async.commit_group;" ::: "memory")
#define CP_WAIT1()  asm volatile("cp.async.wait_group 1;" ::: "memory")

__device__ __forceinline__ void ldsm4(uint32_t* d, uint32_t a) {
    asm volatile("ldmatrix.sync.aligned.m8n8.x4.shared.b16 {%0,%1,%2,%3}, [%4];"
                 : "=r"(d[0]), "=r"(d[1]), "=r"(d[2]), "=r"(d[3]) : "r"(a));
}
__device__ __forceinline__ void ldsm2(uint32_t* d, uint32_t a) {
    asm volatile("ldmatrix.sync.aligned.m8n8.x2.shared.b16 {%0,%1}, [%2];"
                 : "=r"(d[0]), "=r"(d[1]) : "r"(a));
}
__device__ __forceinline__ void mma8(float* c, const uint32_t* a, uint32_t b0, uint32_t b1) {
    asm volatile("mma.sync.aligned.m16n8k8.row.col.f32.tf32.tf32.f32 "
                 "{%0,%1,%2,%3}, {%4,%5,%6,%7}, {%8,%9}, {%0,%1,%2,%3};"
                 : "+f"(c[0]), "+f"(c[1]), "+f"(c[2]), "+f"(c[3])
                 : "r"(a[0]), "r"(a[1]), "r"(a[2]), "r"(a[3]), "r"(b0), "r"(b1));
}

// ---- pre-pass: w[co][ci][tap] -> wt[tap][co][ci] (tf32) ----
__global__ void prep_w(const float* __restrict__ w) {
    int i = blockIdx.x * 256 + threadIdx.x;
    if (i < 9 * 128 * 64) {
        int ci = i & 63, co = (i >> 6) & 127, tap = i >> 13;
        wt_g[i] = f2tf32(w[co * 576 + ci * 9 + tap]);
    }
}

// ---- pre-pass: x[ci][y][col] -> xt[y][col][ci] (tf32), pad cols untouched ----
__global__ void prep_x(const float* __restrict__ x) {
    extern __shared__ float s[];            // [64][225]
    const int y = blockIdx.x, tid = threadIdx.x;
#pragma unroll 4
    for (int ci = 0; ci < 64; ci++)
        if (tid < 224)
            s[ci * 225 + tid] = f2tf32(x[ci * (HW_IN * HW_IN) + y * HW_IN + tid]);
    __syncthreads();
    for (int i = tid; i < 224 * 16; i += 256) {
        int col = i >> 4, q = i & 15;
        float4 v = make_float4(s[(4 * q + 0) * 225 + col], s[(4 * q + 1) * 225 + col],
                               s[(4 * q + 2) * 225 + col], s[(4 * q + 3) * 225 + col]);
        *(float4*)&xt_g[((size_t)y * XT_W + col) * 64 + 4 * q] = v;
    }
}

// ---- main ----
__global__ __launch_bounds__(256, 3)
void conv_main(float* __restrict__ out)
{
    extern __shared__ char smem[];
    const uint32_t sb = smem_u32(smem);
    const int tid = threadIdx.x, wid = tid >> 5, lane = tid & 31;
    const int bx = blockIdx.x, oy = blockIdx.y;
    const int n0 = bx * 112;
    const int co_base = blockIdx.z * 64;

    // per-thread staging slots (constant across chunks)
    uint32_t a_dst[2], b_dst[4];
    int a_src[2], b_src[4];
#pragma unroll
    for (int t = 0; t < 2; t++) {
        int i = tid + t * 256, co = i >> 3, seg = i & 7;
        a_dst[t] = SWZ((uint32_t)(co * 128 + seg * 16));
        a_src[t] = co * 64 + seg * 4;
    }
#pragma unroll
    for (int t = 0; t < 4; t++) {
        int i = tid + t * 256, n = i >> 3, seg = i & 7;
        b_dst[t] = 8192u + SWZ((uint32_t)(n * 128 + seg * 16));
        b_src[t] = n * 64 + seg * 4;
    }

    // mma addressing (R9-validated mapping)
    const int mi = lane >> 3, ri = lane & 7;
    const int m_loc = (wid & 3) * 16;        // 4 M-tiles of 16
    const int n_loc = (wid >> 2) * 56;       // 2 N-tiles of 56
    const uint32_t a_off = (uint32_t)(m_loc + (mi & 1) * 8 + ri) * 128u
                         + (uint32_t)(mi >> 1) * 16u;
    uint32_t b_off4[3];
#pragma unroll
    for (int p = 0; p < 3; p++)
        b_off4[p] = (uint32_t)(n_loc + p * 16 + (mi >> 1) * 8 + ri) * 128u
                  + (uint32_t)(mi & 1) * 16u;
    const uint32_t b_off2 = (uint32_t)(n_loc + 48 + (lane & 7)) * 128u
                          + (uint32_t)((lane >> 3) & 1) * 16u;

    float acc[7][4];
#pragma unroll
    for (int j = 0; j < 7; j++)
#pragma unroll
        for (int q = 0; q < 4; q++) acc[j][q] = 0.0f;

    const float* wbase = wt_g + co_base * 64;

#define ISSUE(c) do {                                                         \
        int _tap = (c) >> 1, _ci0 = ((c) & 1) * 32;                           \
        int _r = _tap / 3, _s = _tap - 3 * _r;                                \
        const float* _as = wbase + _tap * 8192 + _ci0;                        \
        const float* _bs = xt_g + ((size_t)(oy + _r) * XT_W + n0 + _s) * 64 + _ci0; \
        uint32_t _stb = sb + (uint32_t)((c) % 3) * STG_BYTES;                 \
        cp16(_stb + a_dst[0], _as + a_src[0]);                                \
        cp16(_stb + a_dst[1], _as + a_src[1]);                                \
        cp16(_stb + b_dst[0], _bs + b_src[0]);                                \
        cp16(_stb + b_dst[1], _bs + b_src[1]);                                \
        cp16(_stb + b_dst[2], _bs + b_src[2]);                                \
        if (tid < 128) cp16(_stb + b_dst[3], _bs + b_src[3]);                 \
        CP_COMMIT();                                                          \
    } while (0)

    ISSUE(0);
    ISSUE(1);

    int stg = 0;
#pragma unroll 1
    for (int c = 0; c < NCH; c++) {
        CP_WAIT1();             // chunk c landed (only c+1 may be pending)
        __syncthreads();        // all warps done with stage (c-1)%3, data visible
        if (c + 2 < NCH) { ISSUE(c + 2); } else { CP_COMMIT(); }  // keep group count uniform

        const uint32_t ab = sb + (uint32_t)stg * STG_BYTES;
        const uint32_t bb = ab + 8192u;
#pragma unroll
        for (int ks = 0; ks < 4; ks++) {
            const uint32_t kb = (uint32_t)ks * 32u;
            uint32_t af[4], bfr[14];
            ldsm4(af, ab + SWZ(a_off + kb));
            ldsm4(&bfr[0],  bb + SWZ(b_off4[0] + kb));
            ldsm4(&bfr[4],  bb + SWZ(b_off4[1] + kb));
            ldsm4(&bfr[8],  bb + SWZ(b_off4[2] + kb));
            ldsm2(&bfr[12], bb + SWZ(b_off2 + kb));
#pragma unroll
            for (int j = 0; j < 7; j++)
                mma8(acc[j], af, bfr[2 * j], bfr[2 * j + 1]);
        }
        stg++; if (stg == 3) stg = 0;
    }
#undef ISSUE

    // epilogue: direct STG (addresses all even -> float2 aligned)
    const int gid = lane >> 2, tig = lane & 3;
    const int co0 = co_base + m_loc + gid;
    const int co1 = co0 + 8;
#pragma unroll
    for (int j = 0; j < 7; j++) {
        int local = n_loc + j * 8 + tig * 2;
        if (bx == 0 || local < 110) {
            size_t ro = (size_t)oy * HW_OUT + n0 + local;
            *(float2*)&out[(size_t)co0 * OUT_HW + ro] = make_float2(acc[j][0], acc[j][1]);
            *(float2*)&out[(size_t)co1 * OUT_HW + ro] = make_float2(acc[j][2], acc[j][3]);
        }
    }
}

extern "C" void kernel_launch(void* const* d_in, const int* in_sizes, int n_in,
                              void* d_out, int out_size)
{
    const float* x = (const float*)d_in[0];
    const float* w = (const float*)d_in[1];
    if (n_in >= 2 && in_sizes[0] == C_OUT * C_IN * 9 &&
        in_sizes[1] == C_IN * HW_IN * HW_IN) {
        w = (const float*)d_in[0];
        x = (const float*)d_in[1];
    }
    float* out = (float*)d_out;

    cudaFuncSetAttribute(prep_x, cudaFuncAttributeMaxDynamicSharedMemorySize, 64 * 225 * 4);
    cudaFuncSetAttribute(conv_main, cudaFuncAttributeMaxDynamicSharedMemorySize, SM_MAIN);

    prep_w<<<(9 * 128 * 64 + 255) / 256, 256>>>(w);
    prep_x<<<HW_IN, 256, 64 * 225 * 4>>>(x);
    conv_main<<<dim3(2, HW_OUT, 2), 256, SM_MAIN>>>(out);
}